// round 13
// baseline (speedup 1.0000x reference)
#include <cuda_runtime.h>
#include <cuda_bf16.h>
#include <cstdint>

// Problem constants
#define BATCH 4
#define NTOK  1024
#define FDIM  1024
#define HEADS 16
#define HD    64
#define SEQ   2048   // 2*NTOK

// ===========================================================================
// Helpers
// ===========================================================================
__device__ __forceinline__ uint32_t smem_u32(const void* p) {
    uint32_t a;
    asm("{ .reg .u64 t; cvta.to.shared.u64 t, %1; cvt.u32.u64 %0, t; }"
        : "=r"(a) : "l"(p));
    return a;
}
__device__ __forceinline__ void cp16(uint32_t dst, const void* src) {
    asm volatile("cp.async.ca.shared.global [%0], [%1], 16;" :: "r"(dst), "l"(src));
}
#define CP_COMMIT() asm volatile("cp.async.commit_group;" ::: "memory")
#define CP_WAIT(n)  asm volatile("cp.async.wait_group %0;" :: "n"(n) : "memory")

// bf16 tensor-core mma: D(16x8,f32) += A(16x16,bf16) * B(16x8,bf16)
__device__ __forceinline__ void mma_bf16(float* d, const uint32_t* a, const uint32_t* b) {
    asm volatile(
        "mma.sync.aligned.m16n8k16.row.col.f32.bf16.bf16.f32 "
        "{%0,%1,%2,%3}, {%4,%5,%6,%7}, {%8,%9}, {%0,%1,%2,%3};"
        : "+f"(d[0]), "+f"(d[1]), "+f"(d[2]), "+f"(d[3])
        : "r"(a[0]), "r"(a[1]), "r"(a[2]), "r"(a[3]), "r"(b[0]), "r"(b[1]));
}

// pack (x -> lower bf16, y -> upper bf16) hi + residual lo
__device__ __forceinline__ void pack_pair(float x, float y, uint32_t& hi, uint32_t& lo) {
    uint32_t h;
    asm("cvt.rn.bf16x2.f32 %0, %1, %2;" : "=r"(h) : "f"(y), "f"(x));
    float fx = __uint_as_float(h << 16);
    float fy = __uint_as_float(h & 0xFFFF0000u);
    uint32_t l;
    asm("cvt.rn.bf16x2.f32 %0, %1, %2;" : "=r"(l) : "f"(y - fy), "f"(x - fx));
    hi = h; lo = l;
}

// ===========================================================================
// Scratch
// ===========================================================================
__device__ float g_qf[BATCH * NTOK * FDIM];     // fp32 Q (for w0 kernel)
__device__ float g_qs[BATCH * FDIM];
__device__ float g_ks[BATCH * FDIM];
__device__ float g_vs[BATCH * FDIM];
__device__ float g_R1[SEQ];
__device__ float g_w0[BATCH * HEADS * SEQ];     // scene-key weights
// bf16 hi/lo splits
__device__ __nv_bfloat16 g_fhi[BATCH * NTOK * FDIM];
__device__ __nv_bfloat16 g_flo[BATCH * NTOK * FDIM];
__device__ __nv_bfloat16 g_wqh[FDIM * FDIM];
__device__ __nv_bfloat16 g_wql[FDIM * FDIM];
__device__ __nv_bfloat16 g_wkh[FDIM * FDIM];
__device__ __nv_bfloat16 g_wkl[FDIM * FDIM];
__device__ __nv_bfloat16 g_wvh[FDIM * FDIM];
__device__ __nv_bfloat16 g_wvl[FDIM * FDIM];
__device__ __nv_bfloat16 g_woh[FDIM * FDIM];
__device__ __nv_bfloat16 g_wol[FDIM * FDIM];
__device__ __nv_bfloat16 g_qhi[BATCH * NTOK * FDIM];
__device__ __nv_bfloat16 g_qlo[BATCH * NTOK * FDIM];
__device__ __nv_bfloat16 g_khi[BATCH * NTOK * FDIM];
__device__ __nv_bfloat16 g_klo[BATCH * NTOK * FDIM];
__device__ __nv_bfloat16 g_vhi[BATCH * NTOK * FDIM];
__device__ __nv_bfloat16 g_vlo[BATCH * NTOK * FDIM];
__device__ __nv_bfloat16 g_ahi[BATCH * SEQ * FDIM];
__device__ __nv_bfloat16 g_alo[BATCH * SEQ * FDIM];

// ===========================================================================
// Split fp32 -> bf16 hi + lo
// ===========================================================================
__global__ __launch_bounds__(256) void split_kernel(
    const float* __restrict__ x, __nv_bfloat16* __restrict__ hi,
    __nv_bfloat16* __restrict__ lo, int n)
{
    int i = (blockIdx.x * 256 + threadIdx.x) * 4;
    if (i >= n) return;
    float4 v = *(const float4*)(x + i);
    uint32_t h0, l0, h1, l1;
    pack_pair(v.x, v.y, h0, l0);
    pack_pair(v.z, v.w, h1, l1);
    *(uint32_t*)(hi + i)     = h0;
    *(uint32_t*)(hi + i + 2) = h1;
    *(uint32_t*)(lo + i)     = l0;
    *(uint32_t*)(lo + i + 2) = l1;
}

// ===========================================================================
// bf16x3 GEMM via mma.sync (NT): tile 128x128, 4 warps (2x2), warp 64x64.
// Term-reordered mma issue: all three split-term streams independent.
// ===========================================================================
#define GKC   32
#define NCH   (FDIM / GKC)
#define KP    40
#define MAT_B (128 * KP * 2)   // 10240 B
#define BUF_B (4 * MAT_B)      // 40960 B
#define GSM_TOT (2 * BUF_B)    // 81920 B

__global__ __launch_bounds__(128) void gemm_mma(
    const __nv_bfloat16* __restrict__ Ah, const __nv_bfloat16* __restrict__ Al,
    const __nv_bfloat16* __restrict__ Bh, const __nv_bfloat16* __restrict__ Bl,
    const float* __restrict__ bias, float* __restrict__ C,
    __nv_bfloat16* __restrict__ Chi, __nv_bfloat16* __restrict__ Clo, int Ncols)
{
    extern __shared__ char smc[];
    const uint32_t smb = smem_u32(smc);
    const int tid  = threadIdx.x;
    const int wid  = tid >> 5;
    const int lane = tid & 31;
    const int wm = wid >> 1;          // 0..1
    const int wn = wid & 1;           // 0..1
    const int bm = blockIdx.y * 128;
    const int bn = blockIdx.x * 128;

    // Loader: thread t owns row t of A and row t of B (64 bf16 = 8 cp16 each)
    const __nv_bfloat16* gAh = Ah + (size_t)(bm + tid) * FDIM;
    const __nv_bfloat16* gAl = Al + (size_t)(bm + tid) * FDIM;
    const __nv_bfloat16* gBh = Bh + (size_t)(bn + tid) * FDIM;
    const __nv_bfloat16* gBl = Bl + (size_t)(bn + tid) * FDIM;
    const uint32_t soff = tid * (KP * 2);

    float acc[4][8][4];
#pragma unroll
    for (int mt = 0; mt < 4; mt++)
#pragma unroll
        for (int nt = 0; nt < 8; nt++)
#pragma unroll
            for (int k = 0; k < 4; k++) acc[mt][nt][k] = 0.f;

    auto issue = [&](int ck, int bsel) {
        const uint32_t base = smb + bsel * BUF_B + soff;
        const int ge = ck * GKC;
#pragma unroll
        for (int j = 0; j < 4; j++) {
            cp16(base + 0 * MAT_B + j * 16, gAh + ge + j * 8);
            cp16(base + 1 * MAT_B + j * 16, gAl + ge + j * 8);
            cp16(base + 2 * MAT_B + j * 16, gBh + ge + j * 8);
            cp16(base + 3 * MAT_B + j * 16, gBl + ge + j * 8);
        }
    };

    issue(0, 0);
    CP_COMMIT();

    const int fr = lane >> 2;
    const int fc = (lane & 3) * 2;

    for (int c = 0; c < NCH; c++) {
        if (c + 1 < NCH) {
            issue(c + 1, (c + 1) & 1);
            CP_COMMIT();
            CP_WAIT(1);
        } else {
            CP_WAIT(0);
        }
        __syncthreads();

        const __nv_bfloat16* Ah_s = (const __nv_bfloat16*)(smc + (c & 1) * BUF_B + 0 * MAT_B);
        const __nv_bfloat16* Al_s = (const __nv_bfloat16*)(smc + (c & 1) * BUF_B + 1 * MAT_B);
        const __nv_bfloat16* Bh_s = (const __nv_bfloat16*)(smc + (c & 1) * BUF_B + 2 * MAT_B);
        const __nv_bfloat16* Bl_s = (const __nv_bfloat16*)(smc + (c & 1) * BUF_B + 3 * MAT_B);

#pragma unroll
        for (int ks = 0; ks < 2; ks++) {
            const int k0 = ks * 16 + fc;
            uint32_t ah[4][4], al[4][4], bh[8][2], bl[8][2];
#pragma unroll
            for (int mt = 0; mt < 4; mt++) {
                const int r = wm * 64 + mt * 16 + fr;
                ah[mt][0] = *(const uint32_t*)&Ah_s[r * KP + k0];
                ah[mt][1] = *(const uint32_t*)&Ah_s[(r + 8) * KP + k0];
                ah[mt][2] = *(const uint32_t*)&Ah_s[r * KP + k0 + 8];
                ah[mt][3] = *(const uint32_t*)&Ah_s[(r + 8) * KP + k0 + 8];
                al[mt][0] = *(const uint32_t*)&Al_s[r * KP + k0];
                al[mt][1] = *(const uint32_t*)&Al_s[(r + 8) * KP + k0];
                al[mt][2] = *(const uint32_t*)&Al_s[r * KP + k0 + 8];
                al[mt][3] = *(const uint32_t*)&Al_s[(r + 8) * KP + k0 + 8];
            }
#pragma unroll
            for (int nt = 0; nt < 8; nt++) {
                const int n = wn * 64 + nt * 8 + fr;
                bh[nt][0] = *(const uint32_t*)&Bh_s[n * KP + k0];
                bh[nt][1] = *(const uint32_t*)&Bh_s[n * KP + k0 + 8];
                bl[nt][0] = *(const uint32_t*)&Bl_s[n * KP + k0];
                bl[nt][1] = *(const uint32_t*)&Bl_s[n * KP + k0 + 8];
            }
            // term-outer: 32 independent mma per sweep
#pragma unroll
            for (int mt = 0; mt < 4; mt++)
#pragma unroll
                for (int nt = 0; nt < 8; nt++)
                    mma_bf16(acc[mt][nt], ah[mt], bh[nt]);
#pragma unroll
            for (int mt = 0; mt < 4; mt++)
#pragma unroll
                for (int nt = 0; nt < 8; nt++)
                    mma_bf16(acc[mt][nt], ah[mt], bl[nt]);
#pragma unroll
            for (int mt = 0; mt < 4; mt++)
#pragma unroll
                for (int nt = 0; nt < 8; nt++)
                    mma_bf16(acc[mt][nt], al[mt], bh[nt]);
        }
        __syncthreads();
    }

#pragma unroll
    for (int nt = 0; nt < 8; nt++) {
        const int c0 = bn + wn * 64 + nt * 8 + (lane & 3) * 2;
        const float2 bv = *(const float2*)&bias[c0];
#pragma unroll
        for (int mt = 0; mt < 4; mt++) {
            const int r0 = bm + wm * 64 + mt * 16 + (lane >> 2);
            float2 v0 = make_float2(acc[mt][nt][0] + bv.x, acc[mt][nt][1] + bv.y);
            float2 v1 = make_float2(acc[mt][nt][2] + bv.x, acc[mt][nt][3] + bv.y);
            if (C) {
                *(float2*)&C[(size_t)r0 * Ncols + c0]       = v0;
                *(float2*)&C[(size_t)(r0 + 8) * Ncols + c0] = v1;
            }
            if (Chi) {
                uint32_t h0, l0, h1, l1;
                pack_pair(v0.x, v0.y, h0, l0);
                pack_pair(v1.x, v1.y, h1, l1);
                *(uint32_t*)&Chi[(size_t)r0 * Ncols + c0]       = h0;
                *(uint32_t*)&Clo[(size_t)r0 * Ncols + c0]       = l0;
                *(uint32_t*)&Chi[(size_t)(r0 + 8) * Ncols + c0] = h1;
                *(uint32_t*)&Clo[(size_t)(r0 + 8) * Ncols + c0] = l1;
            }
        }
    }
}

// ===========================================================================
// Scene-token QKV (exact fp32)
// ===========================================================================
__global__ __launch_bounds__(256) void scene_qkv_kernel(
    const float* __restrict__ scene,
    const float* __restrict__ Wq, const float* __restrict__ bq,
    const float* __restrict__ Wk, const float* __restrict__ bk,
    const float* __restrict__ Wv, const float* __restrict__ bv,
    float* __restrict__ qs, float* __restrict__ ks, float* __restrict__ vs)
{
    int gw   = (blockIdx.x * 256 + threadIdx.x) >> 5;
    int lane = threadIdx.x & 31;
    int which = gw >> 12;
    int rem   = gw & 4095;
    int b = rem >> 10;
    int j = rem & 1023;

    const float* W; const float* bias; float* out;
    if (which == 0)      { W = Wq; bias = bq; out = qs; }
    else if (which == 1) { W = Wk; bias = bk; out = ks; }
    else                 { W = Wv; bias = bv; out = vs; }

    const float* x = scene + b * FDIM;
    const float* w = W + (size_t)j * FDIM;
    float acc = 0.f;
    for (int k = lane * 4; k < FDIM; k += 128) {
        float4 xv = *(const float4*)(x + k);
        float4 wv = *(const float4*)(w + k);
        acc = fmaf(xv.x, wv.x, acc);
        acc = fmaf(xv.y, wv.y, acc);
        acc = fmaf(xv.z, wv.z, acc);
        acc = fmaf(xv.w, wv.w, acc);
    }
#pragma unroll
    for (int o = 16; o; o >>= 1) acc += __shfl_xor_sync(0xffffffffu, acc, o);
    if (lane == 0) out[b * FDIM + j] = acc + bias[j];
}

// ===========================================================================
// R1[q] = sum_{k<NTOK} exp(rel[q,k])
// ===========================================================================
__global__ __launch_bounds__(256) void r1_kernel(
    const float* __restrict__ rel, float* __restrict__ R1)
{
    int row  = (blockIdx.x * 256 + threadIdx.x) >> 5;
    int lane = threadIdx.x & 31;
    const float* r = rel + (size_t)row * SEQ;
    float acc = 0.f;
    for (int k = lane * 4; k < NTOK; k += 128) {
        float4 v = *(const float4*)(r + k);
        acc += __expf(v.x) + __expf(v.y) + __expf(v.z) + __expf(v.w);
    }
#pragma unroll
    for (int o = 16; o; o >>= 1) acc += __shfl_xor_sync(0xffffffffu, acc, o);
    if (lane == 0) R1[row] = acc;
}

// ===========================================================================
// w0[b,h,q] = exp(q_vec . k_scene / 8) * R1[q]   (one warp per q)
// ===========================================================================
__global__ __launch_bounds__(256) void w0_kernel(
    const float* __restrict__ qf, const float* __restrict__ qs,
    const float* __restrict__ ks, const float* __restrict__ R1,
    float* __restrict__ w0g)
{
    int gw   = (blockIdx.x * 256 + threadIdx.x) >> 5;
    int lane = threadIdx.x & 31;
    int q  = gw & (SEQ - 1);
    int bh = gw >> 11;
    int b  = bh >> 4;
    int h  = bh & 15;
    const float* qv = (q < NTOK) ? qs + b * FDIM + h * HD
                                 : qf + (size_t)(b * NTOK + q - NTOK) * FDIM + h * HD;
    const float* kv = ks + b * FDIM + h * HD;
    float2 a = *(const float2*)(qv + lane * 2);
    float2 c = *(const float2*)(kv + lane * 2);
    float p = a.x * c.x + a.y * c.y;
#pragma unroll
    for (int o = 16; o; o >>= 1) p += __shfl_xor_sync(0xffffffffu, p, o);
    if (lane == 0) w0g[bh * SEQ + q] = __expf(p * 0.125f) * R1[q];
}

// ===========================================================================
// Flash attention via bf16x3 mma.sync, term-reordered issue.
// Block: 128 q rows of one (b,h). 8 warps x 16 q. 8 key-tiles of 128.
// smem: Kh/Kl [128][72] + Vth/Vtl [64][136]  (71680 B)
// ===========================================================================
#define BQ  128
#define BK  128
#define KSP 72
#define VSP 136
#define ASM_TOT ((2 * 128 * KSP + 2 * 64 * VSP) * 2)   // 71680

__global__ __launch_bounds__(256) void attn_mma(
    const __nv_bfloat16* __restrict__ qhi, const __nv_bfloat16* __restrict__ qlo,
    const __nv_bfloat16* __restrict__ khi, const __nv_bfloat16* __restrict__ klo,
    const __nv_bfloat16* __restrict__ vhi, const __nv_bfloat16* __restrict__ vlo,
    const float* __restrict__ qs, const float* __restrict__ vs_scene,
    const float* __restrict__ rel, const float* __restrict__ w0g,
    __nv_bfloat16* __restrict__ ahi, __nv_bfloat16* __restrict__ alo)
{
    extern __shared__ __nv_bfloat16 sb[];
    __nv_bfloat16* Kh  = sb;
    __nv_bfloat16* Kl  = sb + 128 * KSP;
    __nv_bfloat16* Vth = sb + 2 * 128 * KSP;
    __nv_bfloat16* Vtl = Vth + 64 * VSP;
    const uint32_t smb = smem_u32(sb);

    const int tid  = threadIdx.x;
    const int lane = tid & 31;
    const int wid  = tid >> 5;
    const int b  = blockIdx.z, h = blockIdx.y;
    const int q0 = blockIdx.x * BQ;
    const int fr = lane >> 2;
    const int c2 = (lane & 3) * 2;
    const int wq = wid * 16;

    // ---- stage Q into Kh/Kl, extract frags ----
    {
        int r = tid >> 1, half = tid & 1;
        int dbase = half * 32;
        if (q0 < NTOK) {
            const float* src = qs + b * FDIM + h * HD + dbase;
#pragma unroll
            for (int j = 0; j < 16; j++) {
                float2 v = *(const float2*)(src + j * 2);
                uint32_t hh, ll;
                pack_pair(v.x, v.y, hh, ll);
                *(uint32_t*)&Kh[r * KSP + dbase + j * 2] = hh;
                *(uint32_t*)&Kl[r * KSP + dbase + j * 2] = ll;
            }
        } else {
            const __nv_bfloat16* sh = qhi + (size_t)(b * NTOK + q0 - NTOK + r) * FDIM + h * HD + dbase;
            const __nv_bfloat16* sl = qlo + (size_t)(b * NTOK + q0 - NTOK + r) * FDIM + h * HD + dbase;
#pragma unroll
            for (int j = 0; j < 4; j++) {
                *(uint4*)&Kh[r * KSP + dbase + j * 8] = *(const uint4*)(sh + j * 8);
                *(uint4*)&Kl[r * KSP + dbase + j * 8] = *(const uint4*)(sl + j * 8);
            }
        }
    }
    __syncthreads();

    uint32_t qh[4][4], ql[4][4];
#pragma unroll
    for (int ks = 0; ks < 4; ks++) {
        int k0 = ks * 16 + c2;
        qh[ks][0] = *(const uint32_t*)&Kh[(wq + fr) * KSP + k0];
        qh[ks][1] = *(const uint32_t*)&Kh[(wq + fr + 8) * KSP + k0];
        qh[ks][2] = *(const uint32_t*)&Kh[(wq + fr) * KSP + k0 + 8];
        qh[ks][3] = *(const uint32_t*)&Kh[(wq + fr + 8) * KSP + k0 + 8];
        ql[ks][0] = *(const uint32_t*)&Kl[(wq + fr) * KSP + k0];
        ql[ks][1] = *(const uint32_t*)&Kl[(wq + fr + 8) * KSP + k0];
        ql[ks][2] = *(const uint32_t*)&Kl[(wq + fr) * KSP + k0 + 8];
        ql[ks][3] = *(const uint32_t*)&Kl[(wq + fr + 8) * KSP + k0 + 8];
    }

    float oacc[8][4];
#pragma unroll
    for (int nt = 0; nt < 8; nt++)
#pragma unroll
        for (int k = 0; k < 4; k++) oacc[nt][k] = 0.f;
    float den0 = 0.f, den1 = 0.f;

    const float* relp = rel + (size_t)(q0 + wq + fr) * SEQ + NTOK;

    for (int jt = 0; jt < 8; jt++) {
        __syncthreads();
        // K tiles via cp.async
        {
            int r = tid >> 1, half = tid & 1;
            int dbase = half * 32;
            const __nv_bfloat16* gkh = khi + (size_t)(b * NTOK + jt * BK + r) * FDIM + h * HD + dbase;
            const __nv_bfloat16* gkl = klo + (size_t)(b * NTOK + jt * BK + r) * FDIM + h * HD + dbase;
            uint32_t dh = smb + (r * KSP + dbase) * 2;
            uint32_t dl = smb + (128 * KSP + r * KSP + dbase) * 2;
#pragma unroll
            for (int j = 0; j < 4; j++) {
                cp16(dh + j * 16, gkh + j * 8);
                cp16(dl + j * 16, gkl + j * 8);
            }
        }
        CP_COMMIT();
        // V tiles: LDG + transposed STS
        {
            int key = tid & 127;
            int dg  = (tid >> 7) * 32;
            const uint4* gvh = (const uint4*)(vhi + (size_t)(b * NTOK + jt * BK + key) * FDIM + h * HD + dg);
            const uint4* gvl = (const uint4*)(vlo + (size_t)(b * NTOK + jt * BK + key) * FDIM + h * HD + dg);
#pragma unroll
            for (int j = 0; j < 4; j++) {
                uint4 uh = gvh[j];
                uint4 ul = gvl[j];
                const __nv_bfloat16* eh = (const __nv_bfloat16*)&uh;
                const __nv_bfloat16* el = (const __nv_bfloat16*)&ul;
#pragma unroll
                for (int t = 0; t < 8; t++) {
                    Vth[(dg + j * 8 + t) * VSP + key] = eh[t];
                    Vtl[(dg + j * 8 + t) * VSP + key] = el[t];
                }
            }
        }
        CP_WAIT(0);
        __syncthreads();

        // ---- S = QK^T (bf16x3), term-reordered in 8-nt groups ----
        float sacc[16][4];
#pragma unroll
        for (int nt = 0; nt < 16; nt++)
#pragma unroll
            for (int k = 0; k < 4; k++) sacc[nt][k] = 0.f;

#pragma unroll
        for (int ks = 0; ks < 4; ks++) {
            const int k0 = ks * 16 + c2;
#pragma unroll
            for (int g = 0; g < 2; g++) {           // nt groups of 8
                uint32_t bhf[8][2], blf[8][2];
#pragma unroll
                for (int j = 0; j < 8; j++) {
                    const int n = (g * 8 + j) * 8 + fr;
                    bhf[j][0] = *(const uint32_t*)&Kh[n * KSP + k0];
                    bhf[j][1] = *(const uint32_t*)&Kh[n * KSP + k0 + 8];
                    blf[j][0] = *(const uint32_t*)&Kl[n * KSP + k0];
                    blf[j][1] = *(const uint32_t*)&Kl[n * KSP + k0 + 8];
                }
#pragma unroll
                for (int j = 0; j < 8; j++) mma_bf16(sacc[g * 8 + j], qh[ks], bhf[j]);
#pragma unroll
                for (int j = 0; j < 8; j++) mma_bf16(sacc[g * 8 + j], qh[ks], blf[j]);
#pragma unroll
                for (int j = 0; j < 8; j++) mma_bf16(sacc[g * 8 + j], ql[ks], bhf[j]);
            }
        }

        // ---- bias + exp ----
#pragma unroll
        for (int nt = 0; nt < 16; nt++) {
            int col = jt * BK + nt * 8 + c2;
            float2 rb0 = *(const float2*)(relp + col);
            float2 rb1 = *(const float2*)(relp + 8 * SEQ + col);
            sacc[nt][0] = __expf(fmaf(sacc[nt][0], 0.125f, rb0.x));
            sacc[nt][1] = __expf(fmaf(sacc[nt][1], 0.125f, rb0.y));
            sacc[nt][2] = __expf(fmaf(sacc[nt][2], 0.125f, rb1.x));
            sacc[nt][3] = __expf(fmaf(sacc[nt][3], 0.125f, rb1.y));
            den0 += sacc[nt][0] + sacc[nt][1];
            den1 += sacc[nt][2] + sacc[nt][3];
        }

        // ---- O += P V (bf16x3), term-reordered across nt2 ----
#pragma unroll
        for (int ks2 = 0; ks2 < 8; ks2++) {
            const float* e0 = sacc[2 * ks2];
            const float* e1 = sacc[2 * ks2 + 1];
            uint32_t pa_h[4], pa_l[4];
            pack_pair(e0[0], e0[1], pa_h[0], pa_l[0]);
            pack_pair(e0[2], e0[3], pa_h[1], pa_l[1]);
            pack_pair(e1[0], e1[1], pa_h[2], pa_l[2]);
            pack_pair(e1[2], e1[3], pa_h[3], pa_l[3]);
            const int k0 = ks2 * 16 + c2;
            uint32_t vbh[8][2], vbl[8][2];
#pragma unroll
            for (int j = 0; j < 8; j++) {
                const int n = j * 8 + fr;
                vbh[j][0] = *(const uint32_t*)&Vth[n * VSP + k0];
                vbh[j][1] = *(const uint32_t*)&Vth[n * VSP + k0 + 8];
                vbl[j][0] = *(const uint32_t*)&Vtl[n * VSP + k0];
                vbl[j][1] = *(const uint32_t*)&Vtl[n * VSP + k0 + 8];
            }
#pragma unroll
            for (int j = 0; j < 8; j++) mma_bf16(oacc[j], pa_h, vbh[j]);
#pragma unroll
            for (int j = 0; j < 8; j++) mma_bf16(oacc[j], pa_h, vbl[j]);
#pragma unroll
            for (int j = 0; j < 8; j++) mma_bf16(oacc[j], pa_l, vbh[j]);
        }
    }

    // ---- finalize ----
    den0 += __shfl_xor_sync(0xffffffffu, den0, 1);
    den0 += __shfl_xor_sync(0xffffffffu, den0, 2);
    den1 += __shfl_xor_sync(0xffffffffu, den1, 1);
    den1 += __shfl_xor_sync(0xffffffffu, den1, 2);

    const int r0g = q0 + wq + fr;
    const float* w0v = w0g + (b * HEADS + h) * SEQ;
    float wA = w0v[r0g], wB = w0v[r0g + 8];
    float invA = 1.0f / (den0 + wA);
    float invB = 1.0f / (den1 + wB);
    const float* vsc = vs_scene + b * FDIM + h * HD;

#pragma unroll
    for (int nt2 = 0; nt2 < 8; nt2++) {
        int d0 = nt2 * 8 + c2;
        float2 vs2 = *(const float2*)(vsc + d0);
        float ax = (oacc[nt2][0] + wA * vs2.x) * invA;
        float ay = (oacc[nt2][1] + wA * vs2.y) * invA;
        float bx = (oacc[nt2][2] + wB * vs2.x) * invB;
        float by = (oacc[nt2][3] + wB * vs2.y) * invB;
        uint32_t h0, l0, h1, l1;
        pack_pair(ax, ay, h0, l0);
        pack_pair(bx, by, h1, l1);
        size_t baseA = (size_t)(b * SEQ + r0g) * FDIM + h * HD + d0;
        size_t baseB = (size_t)(b * SEQ + r0g + 8) * FDIM + h * HD + d0;
        *(uint32_t*)&ahi[baseA] = h0;
        *(uint32_t*)&alo[baseA] = l0;
        *(uint32_t*)&ahi[baseB] = h1;
        *(uint32_t*)&alo[baseB] = l1;
    }
}

// ===========================================================================
// Launch
// ===========================================================================
extern "C" void kernel_launch(void* const* d_in, const int* in_sizes, int n_in,
                              void* d_out, int out_size)
{
    (void)in_sizes; (void)n_in; (void)out_size;
    const float* feature = (const float*)d_in[0];
    const float* scene   = (const float*)d_in[1];
    const float* rel     = (const float*)d_in[2];
    const float* Wq = (const float*)d_in[3];  const float* bq = (const float*)d_in[4];
    const float* Wk = (const float*)d_in[5];  const float* bk = (const float*)d_in[6];
    const float* Wv = (const float*)d_in[7];  const float* bv = (const float*)d_in[8];
    const float* Wo = (const float*)d_in[9];  const float* bo = (const float*)d_in[10];
    float* out = (float*)d_out;

    float *qf, *qs, *ks, *vs, *R1, *w0;
    cudaGetSymbolAddress((void**)&qf, g_qf);
    cudaGetSymbolAddress((void**)&qs, g_qs);
    cudaGetSymbolAddress((void**)&ks, g_ks);
    cudaGetSymbolAddress((void**)&vs, g_vs);
    cudaGetSymbolAddress((void**)&R1, g_R1);
    cudaGetSymbolAddress((void**)&w0, g_w0);

    __nv_bfloat16 *fhi, *flo, *wqh, *wql, *wkh, *wkl, *wvh, *wvl, *woh, *wol;
    __nv_bfloat16 *qhi, *qlo, *khi, *klo, *vhi, *vlo, *ahi, *alo;
    cudaGetSymbolAddress((void**)&fhi, g_fhi);
    cudaGetSymbolAddress((void**)&flo, g_flo);
    cudaGetSymbolAddress((void**)&wqh, g_wqh);
    cudaGetSymbolAddress((void**)&wql, g_wql);
    cudaGetSymbolAddress((void**)&wkh, g_wkh);
    cudaGetSymbolAddress((void**)&wkl, g_wkl);
    cudaGetSymbolAddress((void**)&wvh, g_wvh);
    cudaGetSymbolAddress((void**)&wvl, g_wvl);
    cudaGetSymbolAddress((void**)&woh, g_woh);
    cudaGetSymbolAddress((void**)&wol, g_wol);
    cudaGetSymbolAddress((void**)&qhi, g_qhi);
    cudaGetSymbolAddress((void**)&qlo, g_qlo);
    cudaGetSymbolAddress((void**)&khi, g_khi);
    cudaGetSymbolAddress((void**)&klo, g_klo);
    cudaGetSymbolAddress((void**)&vhi, g_vhi);
    cudaGetSymbolAddress((void**)&vlo, g_vlo);
    cudaGetSymbolAddress((void**)&ahi, g_ahi);
    cudaGetSymbolAddress((void**)&alo, g_alo);

    cudaFuncSetAttribute(gemm_mma,
                         cudaFuncAttributeMaxDynamicSharedMemorySize, GSM_TOT);
    cudaFuncSetAttribute(attn_mma,
                         cudaFuncAttributeMaxDynamicSharedMemorySize, ASM_TOT);

    const int NF = BATCH * NTOK * FDIM;
    const int NW = FDIM * FDIM;

    // Splits
    split_kernel<<<NF / 1024, 256>>>(feature, fhi, flo, NF);
    split_kernel<<<NW / 1024, 256>>>(Wq, wqh, wql, NW);
    split_kernel<<<NW / 1024, 256>>>(Wk, wkh, wkl, NW);
    split_kernel<<<NW / 1024, 256>>>(Wv, wvh, wvl, NW);
    split_kernel<<<NW / 1024, 256>>>(Wo, woh, wol, NW);

    // Scene QKV + R1
    scene_qkv_kernel<<<1536, 256>>>(scene, Wq, bq, Wk, bk, Wv, bv, qs, ks, vs);
    r1_kernel<<<256, 256>>>(rel, R1);

    // Feature QKV (bf16 hi/lo epilogues; Q also fp32 for w0)
    dim3 gq(FDIM / 128, (BATCH * NTOK) / 128);   // (8, 32)
    gemm_mma<<<gq, 128, GSM_TOT>>>(fhi, flo, wqh, wql, bq, qf,   qhi, qlo, FDIM);
    gemm_mma<<<gq, 128, GSM_TOT>>>(fhi, flo, wkh, wkl, bk, NULL, khi, klo, FDIM);
    gemm_mma<<<gq, 128, GSM_TOT>>>(fhi, flo, wvh, wvl, bv, NULL, vhi, vlo, FDIM);

    // Scene-key closed form weights
    w0_kernel<<<(BATCH * HEADS * SEQ) / 8, 256>>>(qf, qs, ks, R1, w0);

    // Attention (tensor-core)
    dim3 ga(SEQ / BQ, HEADS, BATCH);   // (16, 16, 4)
    attn_mma<<<ga, 256, ASM_TOT>>>(qhi, qlo, khi, klo, vhi, vlo,
                                   qs, vs, rel, w0, ahi, alo);

    // Output projection -> d_out (fp32)
    dim3 go(FDIM / 128, (BATCH * SEQ) / 128);    // (8, 64)
    gemm_mma<<<go, 128, GSM_TOT>>>(ahi, alo, woh, wol, bo, out, NULL, NULL, FDIM);
}

// round 16
// speedup vs baseline: 1.6568x; 1.6568x over previous
#include <cuda_runtime.h>
#include <cuda_fp16.h>
#include <cstdint>

// Problem constants
#define BATCH 4
#define NTOK  1024
#define FDIM  1024
#define HEADS 16
#define HD    64
#define SEQ   2048   // 2*NTOK

// ===========================================================================
// Helpers
// ===========================================================================
__device__ __forceinline__ uint32_t smem_u32(const void* p) {
    uint32_t a;
    asm("{ .reg .u64 t; cvta.to.shared.u64 t, %1; cvt.u32.u64 %0, t; }"
        : "=r"(a) : "l"(p));
    return a;
}
__device__ __forceinline__ void cp16(uint32_t dst, const void* src) {
    asm volatile("cp.async.ca.shared.global [%0], [%1], 16;" :: "r"(dst), "l"(src));
}
#define CP_COMMIT() asm volatile("cp.async.commit_group;" ::: "memory")
#define CP_WAIT(n)  asm volatile("cp.async.wait_group %0;" :: "n"(n) : "memory")

// fp16 tensor-core mma: D(16x8,f32) += A(16x16,f16) * B(16x8,f16)
__device__ __forceinline__ void mma_f16(float* d, const uint32_t* a, const uint32_t* b) {
    asm volatile(
        "mma.sync.aligned.m16n8k16.row.col.f32.f16.f16.f32 "
        "{%0,%1,%2,%3}, {%4,%5,%6,%7}, {%8,%9}, {%0,%1,%2,%3};"
        : "+f"(d[0]), "+f"(d[1]), "+f"(d[2]), "+f"(d[3])
        : "r"(a[0]), "r"(a[1]), "r"(a[2]), "r"(a[3]), "r"(b[0]), "r"(b[1]));
}

// pack (x,y) -> fp16x2 hi + fp16x2 residual lo
__device__ __forceinline__ void pack_pair(float x, float y, uint32_t& hi, uint32_t& lo) {
    __half2 h = __floats2half2_rn(x, y);
    float2 f = __half22float2(h);
    __half2 l = __floats2half2_rn(x - f.x, y - f.y);
    hi = *(uint32_t*)&h;
    lo = *(uint32_t*)&l;
}
// single rounded fp16x2
__device__ __forceinline__ uint32_t pack_one(float x, float y) {
    __half2 h = __floats2half2_rn(x, y);
    return *(uint32_t*)&h;
}

// ===========================================================================
// Scratch
// ===========================================================================
__device__ float g_qf[BATCH * NTOK * FDIM];     // fp32 Q (for w0 kernel)
__device__ float g_qs[BATCH * FDIM];
__device__ float g_ks[BATCH * FDIM];
__device__ float g_vs[BATCH * FDIM];
__device__ float g_R1[SEQ];
__device__ float g_w0[BATCH * HEADS * SEQ];
// fp16 data
__device__ __half g_fhi[BATCH * NTOK * FDIM];   // features hi
__device__ __half g_flo[BATCH * NTOK * FDIM];   // features lo
__device__ __half g_wq[FDIM * FDIM];            // weights (rounded, single)
__device__ __half g_wk[FDIM * FDIM];
__device__ __half g_wv[FDIM * FDIM];
__device__ __half g_wo[FDIM * FDIM];
__device__ __half g_qhi[BATCH * NTOK * FDIM];   // q pair
__device__ __half g_qlo[BATCH * NTOK * FDIM];
__device__ __half g_kh[BATCH * NTOK * FDIM];    // k single
__device__ __half g_vh[BATCH * NTOK * FDIM];    // v single
__device__ __half g_ahi[BATCH * SEQ * FDIM];    // attn out pair
__device__ __half g_alo[BATCH * SEQ * FDIM];

// ===========================================================================
// Split fp32 -> fp16 hi + lo pair
// ===========================================================================
__global__ __launch_bounds__(256) void split_kernel(
    const float* __restrict__ x, __half* __restrict__ hi,
    __half* __restrict__ lo, int n)
{
    int i = (blockIdx.x * 256 + threadIdx.x) * 4;
    if (i >= n) return;
    float4 v = *(const float4*)(x + i);
    uint32_t h0, l0, h1, l1;
    pack_pair(v.x, v.y, h0, l0);
    pack_pair(v.z, v.w, h1, l1);
    *(uint32_t*)(hi + i)     = h0;
    *(uint32_t*)(hi + i + 2) = h1;
    *(uint32_t*)(lo + i)     = l0;
    *(uint32_t*)(lo + i + 2) = l1;
}
// Round fp32 -> single fp16
__global__ __launch_bounds__(256) void round_kernel(
    const float* __restrict__ x, __half* __restrict__ h, int n)
{
    int i = (blockIdx.x * 256 + threadIdx.x) * 4;
    if (i >= n) return;
    float4 v = *(const float4*)(x + i);
    *(uint32_t*)(h + i)     = pack_one(v.x, v.y);
    *(uint32_t*)(h + i + 2) = pack_one(v.z, v.w);
}

// ===========================================================================
// fp16x2 GEMM via mma.sync (NT): C = (Ah+Al) @ Bh^T + bias
// Tile 128x128, 8 warps (2x4), warp 64x32. A pair + B single: 2 mma terms.
// ===========================================================================
#define GKC   32
#define NCH   (FDIM / GKC)
#define KP    40
#define MAT_B (128 * KP * 2)     // 10240 B
#define BUF_B (3 * MAT_B)        // 30720 B (Ah, Al, Bh)
#define GSM_TOT (2 * BUF_B)      // 61440 B

__global__ __launch_bounds__(256) void gemm_mma(
    const __half* __restrict__ Ah, const __half* __restrict__ Al,
    const __half* __restrict__ Bh,
    const float* __restrict__ bias, float* __restrict__ C,
    __half* __restrict__ Chi, __half* __restrict__ Clo, int Ncols)
{
    extern __shared__ char smc[];
    const uint32_t smb = smem_u32(smc);
    const int tid  = threadIdx.x;
    const int wid  = tid >> 5;
    const int lane = tid & 31;
    const int wm = wid >> 2;
    const int wn = wid & 3;
    const int bm = blockIdx.y * 128;
    const int bn = blockIdx.x * 128;

    const int lrow = tid >> 1;
    const int lhalf = tid & 1;
    const __half* gAh = Ah + (size_t)(bm + lrow) * FDIM + lhalf * 16;
    const __half* gAl = Al + (size_t)(bm + lrow) * FDIM + lhalf * 16;
    const __half* gBh = Bh + (size_t)(bn + lrow) * FDIM + lhalf * 16;
    const uint32_t soff = lrow * (KP * 2) + lhalf * 32;

    float acc[4][4][4];
#pragma unroll
    for (int mt = 0; mt < 4; mt++)
#pragma unroll
        for (int nt = 0; nt < 4; nt++)
#pragma unroll
            for (int k = 0; k < 4; k++) acc[mt][nt][k] = 0.f;

    auto issue = [&](int ck, int bsel) {
        const uint32_t base = smb + bsel * BUF_B + soff;
        const int ge = ck * GKC;
        cp16(base + 0 * MAT_B,      gAh + ge);
        cp16(base + 0 * MAT_B + 16, gAh + ge + 8);
        cp16(base + 1 * MAT_B,      gAl + ge);
        cp16(base + 1 * MAT_B + 16, gAl + ge + 8);
        cp16(base + 2 * MAT_B,      gBh + ge);
        cp16(base + 2 * MAT_B + 16, gBh + ge + 8);
    };

    issue(0, 0);
    CP_COMMIT();

    const int fr = lane >> 2;
    const int fc = (lane & 3) * 2;

    for (int c = 0; c < NCH; c++) {
        if (c + 1 < NCH) {
            issue(c + 1, (c + 1) & 1);
            CP_COMMIT();
            CP_WAIT(1);
        } else {
            CP_WAIT(0);
        }
        __syncthreads();

        const __half* Ah_s = (const __half*)(smc + (c & 1) * BUF_B + 0 * MAT_B);
        const __half* Al_s = (const __half*)(smc + (c & 1) * BUF_B + 1 * MAT_B);
        const __half* Bh_s = (const __half*)(smc + (c & 1) * BUF_B + 2 * MAT_B);

#pragma unroll
        for (int ks = 0; ks < 2; ks++) {
            const int k0 = ks * 16 + fc;
            uint32_t ah[4][4], al[4][4], bh[4][2];
#pragma unroll
            for (int mt = 0; mt < 4; mt++) {
                const int r = wm * 64 + mt * 16 + fr;
                ah[mt][0] = *(const uint32_t*)&Ah_s[r * KP + k0];
                ah[mt][1] = *(const uint32_t*)&Ah_s[(r + 8) * KP + k0];
                ah[mt][2] = *(const uint32_t*)&Ah_s[r * KP + k0 + 8];
                ah[mt][3] = *(const uint32_t*)&Ah_s[(r + 8) * KP + k0 + 8];
                al[mt][0] = *(const uint32_t*)&Al_s[r * KP + k0];
                al[mt][1] = *(const uint32_t*)&Al_s[(r + 8) * KP + k0];
                al[mt][2] = *(const uint32_t*)&Al_s[r * KP + k0 + 8];
                al[mt][3] = *(const uint32_t*)&Al_s[(r + 8) * KP + k0 + 8];
            }
#pragma unroll
            for (int nt = 0; nt < 4; nt++) {
                const int n = wn * 32 + nt * 8 + fr;
                bh[nt][0] = *(const uint32_t*)&Bh_s[n * KP + k0];
                bh[nt][1] = *(const uint32_t*)&Bh_s[n * KP + k0 + 8];
            }
#pragma unroll
            for (int mt = 0; mt < 4; mt++)
#pragma unroll
                for (int nt = 0; nt < 4; nt++) {
                    mma_f16(acc[mt][nt], ah[mt], bh[nt]);
                    mma_f16(acc[mt][nt], al[mt], bh[nt]);
                }
        }
        __syncthreads();
    }

#pragma unroll
    for (int nt = 0; nt < 4; nt++) {
        const int c0 = bn + wn * 32 + nt * 8 + (lane & 3) * 2;
        const float2 bv = *(const float2*)&bias[c0];
#pragma unroll
        for (int mt = 0; mt < 4; mt++) {
            const int r0 = bm + wm * 64 + mt * 16 + (lane >> 2);
            float2 v0 = make_float2(acc[mt][nt][0] + bv.x, acc[mt][nt][1] + bv.y);
            float2 v1 = make_float2(acc[mt][nt][2] + bv.x, acc[mt][nt][3] + bv.y);
            if (C) {
                *(float2*)&C[(size_t)r0 * Ncols + c0]       = v0;
                *(float2*)&C[(size_t)(r0 + 8) * Ncols + c0] = v1;
            }
            if (Chi) {
                if (Clo) {
                    uint32_t h0, l0, h1, l1;
                    pack_pair(v0.x, v0.y, h0, l0);
                    pack_pair(v1.x, v1.y, h1, l1);
                    *(uint32_t*)&Chi[(size_t)r0 * Ncols + c0]       = h0;
                    *(uint32_t*)&Clo[(size_t)r0 * Ncols + c0]       = l0;
                    *(uint32_t*)&Chi[(size_t)(r0 + 8) * Ncols + c0] = h1;
                    *(uint32_t*)&Clo[(size_t)(r0 + 8) * Ncols + c0] = l1;
                } else {
                    *(uint32_t*)&Chi[(size_t)r0 * Ncols + c0]       = pack_one(v0.x, v0.y);
                    *(uint32_t*)&Chi[(size_t)(r0 + 8) * Ncols + c0] = pack_one(v1.x, v1.y);
                }
            }
        }
    }
}

// ===========================================================================
// Scene-token QKV (exact fp32)
// ===========================================================================
__global__ __launch_bounds__(256) void scene_qkv_kernel(
    const float* __restrict__ scene,
    const float* __restrict__ Wq, const float* __restrict__ bq,
    const float* __restrict__ Wk, const float* __restrict__ bk,
    const float* __restrict__ Wv, const float* __restrict__ bv,
    float* __restrict__ qs, float* __restrict__ ks, float* __restrict__ vs)
{
    int gw   = (blockIdx.x * 256 + threadIdx.x) >> 5;
    int lane = threadIdx.x & 31;
    int which = gw >> 12;
    int rem   = gw & 4095;
    int b = rem >> 10;
    int j = rem & 1023;

    const float* W; const float* bias; float* out;
    if (which == 0)      { W = Wq; bias = bq; out = qs; }
    else if (which == 1) { W = Wk; bias = bk; out = ks; }
    else                 { W = Wv; bias = bv; out = vs; }

    const float* x = scene + b * FDIM;
    const float* w = W + (size_t)j * FDIM;
    float acc = 0.f;
    for (int k = lane * 4; k < FDIM; k += 128) {
        float4 xv = *(const float4*)(x + k);
        float4 wv = *(const float4*)(w + k);
        acc = fmaf(xv.x, wv.x, acc);
        acc = fmaf(xv.y, wv.y, acc);
        acc = fmaf(xv.z, wv.z, acc);
        acc = fmaf(xv.w, wv.w, acc);
    }
#pragma unroll
    for (int o = 16; o; o >>= 1) acc += __shfl_xor_sync(0xffffffffu, acc, o);
    if (lane == 0) out[b * FDIM + j] = acc + bias[j];
}

// ===========================================================================
// R1[q] = sum_{k<NTOK} exp(rel[q,k])
// ===========================================================================
__global__ __launch_bounds__(256) void r1_kernel(
    const float* __restrict__ rel, float* __restrict__ R1)
{
    int row  = (blockIdx.x * 256 + threadIdx.x) >> 5;
    int lane = threadIdx.x & 31;
    const float* r = rel + (size_t)row * SEQ;
    float acc = 0.f;
    for (int k = lane * 4; k < NTOK; k += 128) {
        float4 v = *(const float4*)(r + k);
        acc += __expf(v.x) + __expf(v.y) + __expf(v.z) + __expf(v.w);
    }
#pragma unroll
    for (int o = 16; o; o >>= 1) acc += __shfl_xor_sync(0xffffffffu, acc, o);
    if (lane == 0) R1[row] = acc;
}

// ===========================================================================
// w0[b,h,q] = exp(q_vec . k_scene / 8) * R1[q]
// ===========================================================================
__global__ __launch_bounds__(256) void w0_kernel(
    const float* __restrict__ qf, const float* __restrict__ qs,
    const float* __restrict__ ks, const float* __restrict__ R1,
    float* __restrict__ w0g)
{
    int gw   = (blockIdx.x * 256 + threadIdx.x) >> 5;
    int lane = threadIdx.x & 31;
    int q  = gw & (SEQ - 1);
    int bh = gw >> 11;
    int b  = bh >> 4;
    int h  = bh & 15;
    const float* qv = (q < NTOK) ? qs + b * FDIM + h * HD
                                 : qf + (size_t)(b * NTOK + q - NTOK) * FDIM + h * HD;
    const float* kv = ks + b * FDIM + h * HD;
    float2 a = *(const float2*)(qv + lane * 2);
    float2 c = *(const float2*)(kv + lane * 2);
    float p = a.x * c.x + a.y * c.y;
#pragma unroll
    for (int o = 16; o; o >>= 1) p += __shfl_xor_sync(0xffffffffu, p, o);
    if (lane == 0) w0g[bh * SEQ + q] = __expf(p * 0.125f) * R1[q];
}

// ===========================================================================
// Flash attention via fp16x2 mma.sync.
// Block: 128 q rows of one (b,h). 8 warps x 16 q. 8 key-tiles of 128.
// QK: (Qh+Ql)Kh (2 terms). PV: (Ph+Pl)Vh (2 terms).
// smem: Kh [128][72] + Vth [64][136]  (35840 B). Q staged in Kh (hi) and
// Vth region (lo, stride QLP=68; 8-byte stores only — 136 B row is not 16B
// aligned for odd rows).
// ===========================================================================
#define BQ  128
#define BK  128
#define KSP 72
#define VSP 136
#define QLP 68    // Ql staging stride inside Vth region (128*68 = 8704 = 64*136)
#define ASM_TOT ((128 * KSP + 64 * VSP) * 2)   // 35840

__global__ __launch_bounds__(256) void attn_mma(
    const __half* __restrict__ qhi, const __half* __restrict__ qlo,
    const __half* __restrict__ kh,  const __half* __restrict__ vh,
    const float* __restrict__ qs, const float* __restrict__ vs_scene,
    const float* __restrict__ rel, const float* __restrict__ w0g,
    __half* __restrict__ ahi, __half* __restrict__ alo)
{
    extern __shared__ __half sb[];
    __half* Kh  = sb;
    __half* Vth = sb + 128 * KSP;
    const uint32_t smb = smem_u32(sb);

    const int tid  = threadIdx.x;
    const int lane = tid & 31;
    const int wid  = tid >> 5;
    const int b  = blockIdx.z, h = blockIdx.y;
    const int q0 = blockIdx.x * BQ;
    const int fr = lane >> 2;
    const int c2 = (lane & 3) * 2;
    const int wq = wid * 16;

    // ---- stage Q: hi into Kh (stride KSP, 16B-aligned rows), lo into the
    //      Vth region (stride QLP, 8B stores only) ----
    {
        int r = tid >> 1, half = tid & 1;
        int dbase = half * 32;
        if (q0 < NTOK) {
            const float* src = qs + b * FDIM + h * HD + dbase;
#pragma unroll
            for (int j = 0; j < 16; j++) {
                float2 v = *(const float2*)(src + j * 2);
                uint32_t hh, ll;
                pack_pair(v.x, v.y, hh, ll);
                *(uint32_t*)&Kh[r * KSP + dbase + j * 2]  = hh;
                *(uint32_t*)&Vth[r * QLP + dbase + j * 2] = ll;
            }
        } else {
            const __half* sh = qhi + (size_t)(b * NTOK + q0 - NTOK + r) * FDIM + h * HD + dbase;
            const __half* sl = qlo + (size_t)(b * NTOK + q0 - NTOK + r) * FDIM + h * HD + dbase;
#pragma unroll
            for (int j = 0; j < 4; j++)
                *(uint4*)&Kh[r * KSP + dbase + j * 8]  = *(const uint4*)(sh + j * 8);
#pragma unroll
            for (int j = 0; j < 8; j++)   // 8B stores: QLP rows are 8B-aligned
                *(uint2*)&Vth[r * QLP + dbase + j * 4] = *(const uint2*)(sl + j * 4);
        }
    }
    __syncthreads();

    uint32_t qh[4][4], ql[4][4];
#pragma unroll
    for (int ks = 0; ks < 4; ks++) {
        int k0 = ks * 16 + c2;
        qh[ks][0] = *(const uint32_t*)&Kh[(wq + fr) * KSP + k0];
        qh[ks][1] = *(const uint32_t*)&Kh[(wq + fr + 8) * KSP + k0];
        qh[ks][2] = *(const uint32_t*)&Kh[(wq + fr) * KSP + k0 + 8];
        qh[ks][3] = *(const uint32_t*)&Kh[(wq + fr + 8) * KSP + k0 + 8];
        ql[ks][0] = *(const uint32_t*)&Vth[(wq + fr) * QLP + k0];
        ql[ks][1] = *(const uint32_t*)&Vth[(wq + fr + 8) * QLP + k0];
        ql[ks][2] = *(const uint32_t*)&Vth[(wq + fr) * QLP + k0 + 8];
        ql[ks][3] = *(const uint32_t*)&Vth[(wq + fr + 8) * QLP + k0 + 8];
    }

    float oacc[8][4];
#pragma unroll
    for (int nt = 0; nt < 8; nt++)
#pragma unroll
        for (int k = 0; k < 4; k++) oacc[nt][k] = 0.f;
    float den0 = 0.f, den1 = 0.f;

    const float* relp = rel + (size_t)(q0 + wq + fr) * SEQ + NTOK;

    for (int jt = 0; jt < 8; jt++) {
        __syncthreads();   // prior tile reads (and Q staging reads) complete
        // K tile via cp.async
        {
            int r = tid >> 1, half = tid & 1;
            int dbase = half * 32;
            const __half* gk = kh + (size_t)(b * NTOK + jt * BK + r) * FDIM + h * HD + dbase;
            uint32_t dh = smb + (r * KSP + dbase) * 2;
            cp16(dh,      gk);
            cp16(dh + 16, gk + 8);
            cp16(dh + 32, gk + 16);
            cp16(dh + 48, gk + 24);
        }
        CP_COMMIT();
        // V tile: LDG + transposed STS
        {
            int key = tid & 127;
            int dg  = (tid >> 7) * 32;
            const uint4* gv = (const uint4*)(vh + (size_t)(b * NTOK + jt * BK + key) * FDIM + h * HD + dg);
#pragma unroll
            for (int j = 0; j < 4; j++) {
                uint4 u = gv[j];
                const __half* e = (const __half*)&u;
#pragma unroll
                for (int t = 0; t < 8; t++)
                    Vth[(dg + j * 8 + t) * VSP + key] = e[t];
            }
        }
        CP_WAIT(0);
        __syncthreads();

        // ---- S = QK^T (2-term fp16) + bias + exp ----
        float sacc[16][4];
#pragma unroll
        for (int nt = 0; nt < 16; nt++) {
#pragma unroll
            for (int k = 0; k < 4; k++) sacc[nt][k] = 0.f;
#pragma unroll
            for (int ks = 0; ks < 4; ks++) {
                int k0 = ks * 16 + c2;
                uint32_t bhf[2];
                bhf[0] = *(const uint32_t*)&Kh[(nt * 8 + fr) * KSP + k0];
                bhf[1] = *(const uint32_t*)&Kh[(nt * 8 + fr) * KSP + k0 + 8];
                mma_f16(sacc[nt], qh[ks], bhf);
                mma_f16(sacc[nt], ql[ks], bhf);
            }
            int col = jt * BK + nt * 8 + c2;
            float2 rb0 = *(const float2*)(relp + col);
            float2 rb1 = *(const float2*)(relp + 8 * SEQ + col);
            sacc[nt][0] = __expf(fmaf(sacc[nt][0], 0.125f, rb0.x));
            sacc[nt][1] = __expf(fmaf(sacc[nt][1], 0.125f, rb0.y));
            sacc[nt][2] = __expf(fmaf(sacc[nt][2], 0.125f, rb1.x));
            sacc[nt][3] = __expf(fmaf(sacc[nt][3], 0.125f, rb1.y));
            den0 += sacc[nt][0] + sacc[nt][1];
            den1 += sacc[nt][2] + sacc[nt][3];
        }

        // ---- O += P V (2-term fp16) ----
#pragma unroll
        for (int ks2 = 0; ks2 < 8; ks2++) {
            const float* e0 = sacc[2 * ks2];
            const float* e1 = sacc[2 * ks2 + 1];
            uint32_t pa_h[4], pa_l[4];
            pack_pair(e0[0], e0[1], pa_h[0], pa_l[0]);
            pack_pair(e0[2], e0[3], pa_h[1], pa_l[1]);
            pack_pair(e1[0], e1[1], pa_h[2], pa_l[2]);
            pack_pair(e1[2], e1[3], pa_h[3], pa_l[3]);
            const int k0 = ks2 * 16 + c2;
#pragma unroll
            for (int nt2 = 0; nt2 < 8; nt2++) {
                uint32_t vb[2];
                vb[0] = *(const uint32_t*)&Vth[(nt2 * 8 + fr) * VSP + k0];
                vb[1] = *(const uint32_t*)&Vth[(nt2 * 8 + fr) * VSP + k0 + 8];
                mma_f16(oacc[nt2], pa_h, vb);
                mma_f16(oacc[nt2], pa_l, vb);
            }
        }
    }

    // ---- finalize ----
    den0 += __shfl_xor_sync(0xffffffffu, den0, 1);
    den0 += __shfl_xor_sync(0xffffffffu, den0, 2);
    den1 += __shfl_xor_sync(0xffffffffu, den1, 1);
    den1 += __shfl_xor_sync(0xffffffffu, den1, 2);

    const int r0g = q0 + wq + fr;
    const float* w0v = w0g + (b * HEADS + h) * SEQ;
    float wA = w0v[r0g], wB = w0v[r0g + 8];
    float invA = 1.0f / (den0 + wA);
    float invB = 1.0f / (den1 + wB);
    const float* vsc = vs_scene + b * FDIM + h * HD;

#pragma unroll
    for (int nt2 = 0; nt2 < 8; nt2++) {
        int d0 = nt2 * 8 + c2;
        float2 vs2 = *(const float2*)(vsc + d0);
        float ax = (oacc[nt2][0] + wA * vs2.x) * invA;
        float ay = (oacc[nt2][1] + wA * vs2.y) * invA;
        float bx = (oacc[nt2][2] + wB * vs2.x) * invB;
        float by = (oacc[nt2][3] + wB * vs2.y) * invB;
        uint32_t h0, l0, h1, l1;
        pack_pair(ax, ay, h0, l0);
        pack_pair(bx, by, h1, l1);
        size_t baseA = (size_t)(b * SEQ + r0g) * FDIM + h * HD + d0;
        size_t baseB = (size_t)(b * SEQ + r0g + 8) * FDIM + h * HD + d0;
        *(uint32_t*)&ahi[baseA] = h0;
        *(uint32_t*)&alo[baseA] = l0;
        *(uint32_t*)&ahi[baseB] = h1;
        *(uint32_t*)&alo[baseB] = l1;
    }
}

// ===========================================================================
// Launch
// ===========================================================================
extern "C" void kernel_launch(void* const* d_in, const int* in_sizes, int n_in,
                              void* d_out, int out_size)
{
    (void)in_sizes; (void)n_in; (void)out_size;
    const float* feature = (const float*)d_in[0];
    const float* scene   = (const float*)d_in[1];
    const float* rel     = (const float*)d_in[2];
    const float* Wq = (const float*)d_in[3];  const float* bq = (const float*)d_in[4];
    const float* Wk = (const float*)d_in[5];  const float* bk = (const float*)d_in[6];
    const float* Wv = (const float*)d_in[7];  const float* bv = (const float*)d_in[8];
    const float* Wo = (const float*)d_in[9];  const float* bo = (const float*)d_in[10];
    float* out = (float*)d_out;

    float *qf, *qs, *ks, *vs, *R1, *w0;
    cudaGetSymbolAddress((void**)&qf, g_qf);
    cudaGetSymbolAddress((void**)&qs, g_qs);
    cudaGetSymbolAddress((void**)&ks, g_ks);
    cudaGetSymbolAddress((void**)&vs, g_vs);
    cudaGetSymbolAddress((void**)&R1, g_R1);
    cudaGetSymbolAddress((void**)&w0, g_w0);

    __half *fhi, *flo, *wq, *wk, *wv, *wo;
    __half *qhi, *qlo, *kh, *vh, *ahi, *alo;
    cudaGetSymbolAddress((void**)&fhi, g_fhi);
    cudaGetSymbolAddress((void**)&flo, g_flo);
    cudaGetSymbolAddress((void**)&wq,  g_wq);
    cudaGetSymbolAddress((void**)&wk,  g_wk);
    cudaGetSymbolAddress((void**)&wv,  g_wv);
    cudaGetSymbolAddress((void**)&wo,  g_wo);
    cudaGetSymbolAddress((void**)&qhi, g_qhi);
    cudaGetSymbolAddress((void**)&qlo, g_qlo);
    cudaGetSymbolAddress((void**)&kh,  g_kh);
    cudaGetSymbolAddress((void**)&vh,  g_vh);
    cudaGetSymbolAddress((void**)&ahi, g_ahi);
    cudaGetSymbolAddress((void**)&alo, g_alo);

    cudaFuncSetAttribute(gemm_mma,
                         cudaFuncAttributeMaxDynamicSharedMemorySize, GSM_TOT);
    cudaFuncSetAttribute(attn_mma,
                         cudaFuncAttributeMaxDynamicSharedMemorySize, ASM_TOT);

    const int NF = BATCH * NTOK * FDIM;
    const int NW = FDIM * FDIM;

    // Splits / rounds
    split_kernel<<<NF / 1024, 256>>>(feature, fhi, flo, NF);
    round_kernel<<<NW / 1024, 256>>>(Wq, wq, NW);
    round_kernel<<<NW / 1024, 256>>>(Wk, wk, NW);
    round_kernel<<<NW / 1024, 256>>>(Wv, wv, NW);
    round_kernel<<<NW / 1024, 256>>>(Wo, wo, NW);

    // Scene QKV + R1
    scene_qkv_kernel<<<1536, 256>>>(scene, Wq, bq, Wk, bk, Wv, bv, qs, ks, vs);
    r1_kernel<<<256, 256>>>(rel, R1);

    // Feature QKV: q -> fp32 + fp16 pair; k, v -> single fp16
    dim3 gq(FDIM / 128, (BATCH * NTOK) / 128);   // (8, 32)
    gemm_mma<<<gq, 256, GSM_TOT>>>(fhi, flo, wq, bq, qf,   qhi, qlo,  FDIM);
    gemm_mma<<<gq, 256, GSM_TOT>>>(fhi, flo, wk, bk, NULL, kh,  NULL, FDIM);
    gemm_mma<<<gq, 256, GSM_TOT>>>(fhi, flo, wv, bv, NULL, vh,  NULL, FDIM);

    // Scene-key closed form weights
    w0_kernel<<<(BATCH * HEADS * SEQ) / 8, 256>>>(qf, qs, ks, R1, w0);

    // Attention (tensor-core, fp16x2)
    dim3 ga(SEQ / BQ, HEADS, BATCH);   // (16, 16, 4)
    attn_mma<<<ga, 256, ASM_TOT>>>(qhi, qlo, kh, vh, qs, vs, rel, w0, ahi, alo);

    // Output projection -> d_out (fp32)
    dim3 go(FDIM / 128, (BATCH * SEQ) / 128);    // (8, 64)
    gemm_mma<<<go, 256, GSM_TOT>>>(ahi, alo, wo, bo, out, NULL, NULL, FDIM);
}

// round 17
// speedup vs baseline: 1.8031x; 1.0883x over previous
#include <cuda_runtime.h>
#include <cuda_fp16.h>
#include <cstdint>

// Problem constants
#define BATCH 4
#define NTOK  1024
#define FDIM  1024
#define HEADS 16
#define HD    64
#define SEQ   2048   // 2*NTOK

// ===========================================================================
// Helpers
// ===========================================================================
__device__ __forceinline__ uint32_t smem_u32(const void* p) {
    uint32_t a;
    asm("{ .reg .u64 t; cvta.to.shared.u64 t, %1; cvt.u32.u64 %0, t; }"
        : "=r"(a) : "l"(p));
    return a;
}
__device__ __forceinline__ void cp16(uint32_t dst, const void* src) {
    asm volatile("cp.async.ca.shared.global [%0], [%1], 16;" :: "r"(dst), "l"(src));
}
#define CP_COMMIT() asm volatile("cp.async.commit_group;" ::: "memory")
#define CP_WAIT(n)  asm volatile("cp.async.wait_group %0;" :: "n"(n) : "memory")

// fp16 tensor-core mma: D(16x8,f32) += A(16x16,f16) * B(16x8,f16)
__device__ __forceinline__ void mma_f16(float* d, const uint32_t* a, const uint32_t* b) {
    asm volatile(
        "mma.sync.aligned.m16n8k16.row.col.f32.f16.f16.f32 "
        "{%0,%1,%2,%3}, {%4,%5,%6,%7}, {%8,%9}, {%0,%1,%2,%3};"
        : "+f"(d[0]), "+f"(d[1]), "+f"(d[2]), "+f"(d[3])
        : "r"(a[0]), "r"(a[1]), "r"(a[2]), "r"(a[3]), "r"(b[0]), "r"(b[1]));
}

// pack (x,y) -> fp16x2 hi + fp16x2 residual lo
__device__ __forceinline__ void pack_pair(float x, float y, uint32_t& hi, uint32_t& lo) {
    __half2 h = __floats2half2_rn(x, y);
    float2 f = __half22float2(h);
    __half2 l = __floats2half2_rn(x - f.x, y - f.y);
    hi = *(uint32_t*)&h;
    lo = *(uint32_t*)&l;
}
// single rounded fp16x2
__device__ __forceinline__ uint32_t pack_one(float x, float y) {
    __half2 h = __floats2half2_rn(x, y);
    return *(uint32_t*)&h;
}

// ===========================================================================
// Scratch
// ===========================================================================
__device__ float g_qf[BATCH * NTOK * FDIM];     // fp32 Q (for w0 kernel)
__device__ float g_qs[BATCH * FDIM];
__device__ float g_ks[BATCH * FDIM];
__device__ float g_vs[BATCH * FDIM];
__device__ float g_R1[SEQ];
__device__ float g_w0[BATCH * HEADS * SEQ];
// fp16 data
__device__ __half g_fhi[BATCH * NTOK * FDIM];   // features hi
__device__ __half g_flo[BATCH * NTOK * FDIM];   // features lo
__device__ __half g_wq[FDIM * FDIM];            // weights (rounded, single)
__device__ __half g_wk[FDIM * FDIM];
__device__ __half g_wv[FDIM * FDIM];
__device__ __half g_wo[FDIM * FDIM];
__device__ __half g_qhi[BATCH * NTOK * FDIM];   // q pair
__device__ __half g_qlo[BATCH * NTOK * FDIM];
__device__ __half g_kh[BATCH * NTOK * FDIM];    // k single
__device__ __half g_vh[BATCH * NTOK * FDIM];    // v single
__device__ __half g_ahi[BATCH * SEQ * FDIM];    // attn out (single)

// ===========================================================================
// Split fp32 -> fp16 hi + lo pair
// ===========================================================================
__global__ __launch_bounds__(256) void split_kernel(
    const float* __restrict__ x, __half* __restrict__ hi,
    __half* __restrict__ lo, int n)
{
    int i = (blockIdx.x * 256 + threadIdx.x) * 4;
    if (i >= n) return;
    float4 v = *(const float4*)(x + i);
    uint32_t h0, l0, h1, l1;
    pack_pair(v.x, v.y, h0, l0);
    pack_pair(v.z, v.w, h1, l1);
    *(uint32_t*)(hi + i)     = h0;
    *(uint32_t*)(hi + i + 2) = h1;
    *(uint32_t*)(lo + i)     = l0;
    *(uint32_t*)(lo + i + 2) = l1;
}
// Round 4 weight matrices fp32 -> single fp16 in one launch (grid.y selects)
__global__ __launch_bounds__(256) void round4_kernel(
    const float* __restrict__ x0, __half* __restrict__ h0_,
    const float* __restrict__ x1, __half* __restrict__ h1_,
    const float* __restrict__ x2, __half* __restrict__ h2_,
    const float* __restrict__ x3, __half* __restrict__ h3_, int n)
{
    const float* x; __half* h;
    switch (blockIdx.y) {
        case 0:  x = x0; h = h0_; break;
        case 1:  x = x1; h = h1_; break;
        case 2:  x = x2; h = h2_; break;
        default: x = x3; h = h3_; break;
    }
    int i = (blockIdx.x * 256 + threadIdx.x) * 4;
    if (i >= n) return;
    float4 v = *(const float4*)(x + i);
    *(uint32_t*)(h + i)     = pack_one(v.x, v.y);
    *(uint32_t*)(h + i + 2) = pack_one(v.z, v.w);
}

// ===========================================================================
// fp16 GEMM via mma.sync (NT): C = (Ah [+ Al]) @ Bh^T + bias
// Tile 128x128, 8 warps (2x4), warp 64x32. Al == NULL -> 1-term.
// ===========================================================================
#define GKC   32
#define NCH   (FDIM / GKC)
#define KP    40
#define MAT_B (128 * KP * 2)     // 10240 B
#define BUF_B (3 * MAT_B)        // 30720 B (Ah, Al, Bh)
#define GSM_TOT (2 * BUF_B)      // 61440 B

__global__ __launch_bounds__(256) void gemm_mma(
    const __half* __restrict__ Ah, const __half* __restrict__ Al,
    const __half* __restrict__ Bh,
    const float* __restrict__ bias, float* __restrict__ C,
    __half* __restrict__ Chi, __half* __restrict__ Clo, int Ncols)
{
    extern __shared__ char smc[];
    const uint32_t smb = smem_u32(smc);
    const int tid  = threadIdx.x;
    const int wid  = tid >> 5;
    const int lane = tid & 31;
    const int wm = wid >> 2;
    const int wn = wid & 3;
    const int bm = blockIdx.y * 128;
    const int bn = blockIdx.x * 128;
    const bool two_term = (Al != NULL);

    const int lrow = tid >> 1;
    const int lhalf = tid & 1;
    const __half* gAh = Ah + (size_t)(bm + lrow) * FDIM + lhalf * 16;
    const __half* gAl = two_term ? Al + (size_t)(bm + lrow) * FDIM + lhalf * 16 : gAh;
    const __half* gBh = Bh + (size_t)(bn + lrow) * FDIM + lhalf * 16;
    const uint32_t soff = lrow * (KP * 2) + lhalf * 32;

    float acc[4][4][4];
#pragma unroll
    for (int mt = 0; mt < 4; mt++)
#pragma unroll
        for (int nt = 0; nt < 4; nt++)
#pragma unroll
            for (int k = 0; k < 4; k++) acc[mt][nt][k] = 0.f;

    auto issue = [&](int ck, int bsel) {
        const uint32_t base = smb + bsel * BUF_B + soff;
        const int ge = ck * GKC;
        cp16(base + 0 * MAT_B,      gAh + ge);
        cp16(base + 0 * MAT_B + 16, gAh + ge + 8);
        if (two_term) {
            cp16(base + 1 * MAT_B,      gAl + ge);
            cp16(base + 1 * MAT_B + 16, gAl + ge + 8);
        }
        cp16(base + 2 * MAT_B,      gBh + ge);
        cp16(base + 2 * MAT_B + 16, gBh + ge + 8);
    };

    issue(0, 0);
    CP_COMMIT();

    const int fr = lane >> 2;
    const int fc = (lane & 3) * 2;

    for (int c = 0; c < NCH; c++) {
        if (c + 1 < NCH) {
            issue(c + 1, (c + 1) & 1);
            CP_COMMIT();
            CP_WAIT(1);
        } else {
            CP_WAIT(0);
        }
        __syncthreads();

        const __half* Ah_s = (const __half*)(smc + (c & 1) * BUF_B + 0 * MAT_B);
        const __half* Al_s = (const __half*)(smc + (c & 1) * BUF_B + 1 * MAT_B);
        const __half* Bh_s = (const __half*)(smc + (c & 1) * BUF_B + 2 * MAT_B);

#pragma unroll
        for (int ks = 0; ks < 2; ks++) {
            const int k0 = ks * 16 + fc;
            uint32_t ah[4][4], al[4][4], bh[4][2];
#pragma unroll
            for (int mt = 0; mt < 4; mt++) {
                const int r = wm * 64 + mt * 16 + fr;
                ah[mt][0] = *(const uint32_t*)&Ah_s[r * KP + k0];
                ah[mt][1] = *(const uint32_t*)&Ah_s[(r + 8) * KP + k0];
                ah[mt][2] = *(const uint32_t*)&Ah_s[r * KP + k0 + 8];
                ah[mt][3] = *(const uint32_t*)&Ah_s[(r + 8) * KP + k0 + 8];
                if (two_term) {
                    al[mt][0] = *(const uint32_t*)&Al_s[r * KP + k0];
                    al[mt][1] = *(const uint32_t*)&Al_s[(r + 8) * KP + k0];
                    al[mt][2] = *(const uint32_t*)&Al_s[r * KP + k0 + 8];
                    al[mt][3] = *(const uint32_t*)&Al_s[(r + 8) * KP + k0 + 8];
                }
            }
#pragma unroll
            for (int nt = 0; nt < 4; nt++) {
                const int n = wn * 32 + nt * 8 + fr;
                bh[nt][0] = *(const uint32_t*)&Bh_s[n * KP + k0];
                bh[nt][1] = *(const uint32_t*)&Bh_s[n * KP + k0 + 8];
            }
#pragma unroll
            for (int mt = 0; mt < 4; mt++)
#pragma unroll
                for (int nt = 0; nt < 4; nt++) {
                    mma_f16(acc[mt][nt], ah[mt], bh[nt]);
                    if (two_term) mma_f16(acc[mt][nt], al[mt], bh[nt]);
                }
        }
        __syncthreads();
    }

#pragma unroll
    for (int nt = 0; nt < 4; nt++) {
        const int c0 = bn + wn * 32 + nt * 8 + (lane & 3) * 2;
        const float2 bv = *(const float2*)&bias[c0];
#pragma unroll
        for (int mt = 0; mt < 4; mt++) {
            const int r0 = bm + wm * 64 + mt * 16 + (lane >> 2);
            float2 v0 = make_float2(acc[mt][nt][0] + bv.x, acc[mt][nt][1] + bv.y);
            float2 v1 = make_float2(acc[mt][nt][2] + bv.x, acc[mt][nt][3] + bv.y);
            if (C) {
                *(float2*)&C[(size_t)r0 * Ncols + c0]       = v0;
                *(float2*)&C[(size_t)(r0 + 8) * Ncols + c0] = v1;
            }
            if (Chi) {
                if (Clo) {
                    uint32_t h0, l0, h1, l1;
                    pack_pair(v0.x, v0.y, h0, l0);
                    pack_pair(v1.x, v1.y, h1, l1);
                    *(uint32_t*)&Chi[(size_t)r0 * Ncols + c0]       = h0;
                    *(uint32_t*)&Clo[(size_t)r0 * Ncols + c0]       = l0;
                    *(uint32_t*)&Chi[(size_t)(r0 + 8) * Ncols + c0] = h1;
                    *(uint32_t*)&Clo[(size_t)(r0 + 8) * Ncols + c0] = l1;
                } else {
                    *(uint32_t*)&Chi[(size_t)r0 * Ncols + c0]       = pack_one(v0.x, v0.y);
                    *(uint32_t*)&Chi[(size_t)(r0 + 8) * Ncols + c0] = pack_one(v1.x, v1.y);
                }
            }
        }
    }
}

// ===========================================================================
// Scene-token QKV (exact fp32)
// ===========================================================================
__global__ __launch_bounds__(256) void scene_qkv_kernel(
    const float* __restrict__ scene,
    const float* __restrict__ Wq, const float* __restrict__ bq,
    const float* __restrict__ Wk, const float* __restrict__ bk,
    const float* __restrict__ Wv, const float* __restrict__ bv,
    float* __restrict__ qs, float* __restrict__ ks, float* __restrict__ vs)
{
    int gw   = (blockIdx.x * 256 + threadIdx.x) >> 5;
    int lane = threadIdx.x & 31;
    int which = gw >> 12;
    int rem   = gw & 4095;
    int b = rem >> 10;
    int j = rem & 1023;

    const float* W; const float* bias; float* out;
    if (which == 0)      { W = Wq; bias = bq; out = qs; }
    else if (which == 1) { W = Wk; bias = bk; out = ks; }
    else                 { W = Wv; bias = bv; out = vs; }

    const float* x = scene + b * FDIM;
    const float* w = W + (size_t)j * FDIM;
    float acc = 0.f;
    for (int k = lane * 4; k < FDIM; k += 128) {
        float4 xv = *(const float4*)(x + k);
        float4 wv = *(const float4*)(w + k);
        acc = fmaf(xv.x, wv.x, acc);
        acc = fmaf(xv.y, wv.y, acc);
        acc = fmaf(xv.z, wv.z, acc);
        acc = fmaf(xv.w, wv.w, acc);
    }
#pragma unroll
    for (int o = 16; o; o >>= 1) acc += __shfl_xor_sync(0xffffffffu, acc, o);
    if (lane == 0) out[b * FDIM + j] = acc + bias[j];
}

// ===========================================================================
// R1[q] = sum_{k<NTOK} exp(rel[q,k])
// ===========================================================================
__global__ __launch_bounds__(256) void r1_kernel(
    const float* __restrict__ rel, float* __restrict__ R1)
{
    int row  = (blockIdx.x * 256 + threadIdx.x) >> 5;
    int lane = threadIdx.x & 31;
    const float* r = rel + (size_t)row * SEQ;
    float acc = 0.f;
    for (int k = lane * 4; k < NTOK; k += 128) {
        float4 v = *(const float4*)(r + k);
        acc += __expf(v.x) + __expf(v.y) + __expf(v.z) + __expf(v.w);
    }
#pragma unroll
    for (int o = 16; o; o >>= 1) acc += __shfl_xor_sync(0xffffffffu, acc, o);
    if (lane == 0) R1[row] = acc;
}

// ===========================================================================
// w0[b,h,q] = exp(q_vec . k_scene / 8) * R1[q]
// ===========================================================================
__global__ __launch_bounds__(256) void w0_kernel(
    const float* __restrict__ qf, const float* __restrict__ qs,
    const float* __restrict__ ks, const float* __restrict__ R1,
    float* __restrict__ w0g)
{
    int gw   = (blockIdx.x * 256 + threadIdx.x) >> 5;
    int lane = threadIdx.x & 31;
    int q  = gw & (SEQ - 1);
    int bh = gw >> 11;
    int b  = bh >> 4;
    int h  = bh & 15;
    const float* qv = (q < NTOK) ? qs + b * FDIM + h * HD
                                 : qf + (size_t)(b * NTOK + q - NTOK) * FDIM + h * HD;
    const float* kv = ks + b * FDIM + h * HD;
    float2 a = *(const float2*)(qv + lane * 2);
    float2 c = *(const float2*)(kv + lane * 2);
    float p = a.x * c.x + a.y * c.y;
#pragma unroll
    for (int o = 16; o; o >>= 1) p += __shfl_xor_sync(0xffffffffu, p, o);
    if (lane == 0) w0g[bh * SEQ + q] = __expf(p * 0.125f) * R1[q];
}

// ===========================================================================
// Flash attention via fp16 mma.sync.
// QK: (Qh+Ql)Kh (2 terms — exp-amplified, keep precise).
// PV: P_single * Vh (1 term — linear).
// Output: single fp16 (ahi only).
// smem: Kh [128][72] + Vth [64][136]  (35840 B). Q staged in Kh (hi) and
// Vth region (lo, stride QLP=68; 8-byte stores only).
// ===========================================================================
#define BQ  128
#define BK  128
#define KSP 72
#define VSP 136
#define QLP 68
#define ASM_TOT ((128 * KSP + 64 * VSP) * 2)   // 35840

__global__ __launch_bounds__(256) void attn_mma(
    const __half* __restrict__ qhi, const __half* __restrict__ qlo,
    const __half* __restrict__ kh,  const __half* __restrict__ vh,
    const float* __restrict__ qs, const float* __restrict__ vs_scene,
    const float* __restrict__ rel, const float* __restrict__ w0g,
    __half* __restrict__ ahi)
{
    extern __shared__ __half sb[];
    __half* Kh  = sb;
    __half* Vth = sb + 128 * KSP;
    const uint32_t smb = smem_u32(sb);

    const int tid  = threadIdx.x;
    const int lane = tid & 31;
    const int wid  = tid >> 5;
    const int b  = blockIdx.z, h = blockIdx.y;
    const int q0 = blockIdx.x * BQ;
    const int fr = lane >> 2;
    const int c2 = (lane & 3) * 2;
    const int wq = wid * 16;

    // ---- stage Q: hi into Kh (16B rows), lo into Vth region (8B stores) ----
    {
        int r = tid >> 1, half = tid & 1;
        int dbase = half * 32;
        if (q0 < NTOK) {
            const float* src = qs + b * FDIM + h * HD + dbase;
#pragma unroll
            for (int j = 0; j < 16; j++) {
                float2 v = *(const float2*)(src + j * 2);
                uint32_t hh, ll;
                pack_pair(v.x, v.y, hh, ll);
                *(uint32_t*)&Kh[r * KSP + dbase + j * 2]  = hh;
                *(uint32_t*)&Vth[r * QLP + dbase + j * 2] = ll;
            }
        } else {
            const __half* sh = qhi + (size_t)(b * NTOK + q0 - NTOK + r) * FDIM + h * HD + dbase;
            const __half* sl = qlo + (size_t)(b * NTOK + q0 - NTOK + r) * FDIM + h * HD + dbase;
#pragma unroll
            for (int j = 0; j < 4; j++)
                *(uint4*)&Kh[r * KSP + dbase + j * 8]  = *(const uint4*)(sh + j * 8);
#pragma unroll
            for (int j = 0; j < 8; j++)
                *(uint2*)&Vth[r * QLP + dbase + j * 4] = *(const uint2*)(sl + j * 4);
        }
    }
    __syncthreads();

    uint32_t qh[4][4], ql[4][4];
#pragma unroll
    for (int ks = 0; ks < 4; ks++) {
        int k0 = ks * 16 + c2;
        qh[ks][0] = *(const uint32_t*)&Kh[(wq + fr) * KSP + k0];
        qh[ks][1] = *(const uint32_t*)&Kh[(wq + fr + 8) * KSP + k0];
        qh[ks][2] = *(const uint32_t*)&Kh[(wq + fr) * KSP + k0 + 8];
        qh[ks][3] = *(const uint32_t*)&Kh[(wq + fr + 8) * KSP + k0 + 8];
        ql[ks][0] = *(const uint32_t*)&Vth[(wq + fr) * QLP + k0];
        ql[ks][1] = *(const uint32_t*)&Vth[(wq + fr + 8) * QLP + k0];
        ql[ks][2] = *(const uint32_t*)&Vth[(wq + fr) * QLP + k0 + 8];
        ql[ks][3] = *(const uint32_t*)&Vth[(wq + fr + 8) * QLP + k0 + 8];
    }

    float oacc[8][4];
#pragma unroll
    for (int nt = 0; nt < 8; nt++)
#pragma unroll
        for (int k = 0; k < 4; k++) oacc[nt][k] = 0.f;
    float den0 = 0.f, den1 = 0.f;

    const float* relp = rel + (size_t)(q0 + wq + fr) * SEQ + NTOK;

    for (int jt = 0; jt < 8; jt++) {
        __syncthreads();
        // K tile via cp.async
        {
            int r = tid >> 1, half = tid & 1;
            int dbase = half * 32;
            const __half* gk = kh + (size_t)(b * NTOK + jt * BK + r) * FDIM + h * HD + dbase;
            uint32_t dh = smb + (r * KSP + dbase) * 2;
            cp16(dh,      gk);
            cp16(dh + 16, gk + 8);
            cp16(dh + 32, gk + 16);
            cp16(dh + 48, gk + 24);
        }
        CP_COMMIT();
        // V tile: LDG + transposed STS
        {
            int key = tid & 127;
            int dg  = (tid >> 7) * 32;
            const uint4* gv = (const uint4*)(vh + (size_t)(b * NTOK + jt * BK + key) * FDIM + h * HD + dg);
#pragma unroll
            for (int j = 0; j < 4; j++) {
                uint4 u = gv[j];
                const __half* e = (const __half*)&u;
#pragma unroll
                for (int t = 0; t < 8; t++)
                    Vth[(dg + j * 8 + t) * VSP + key] = e[t];
            }
        }
        CP_WAIT(0);
        __syncthreads();

        // ---- S = QK^T (2-term fp16) + bias + exp ----
        float sacc[16][4];
#pragma unroll
        for (int nt = 0; nt < 16; nt++) {
#pragma unroll
            for (int k = 0; k < 4; k++) sacc[nt][k] = 0.f;
#pragma unroll
            for (int ks = 0; ks < 4; ks++) {
                int k0 = ks * 16 + c2;
                uint32_t bhf[2];
                bhf[0] = *(const uint32_t*)&Kh[(nt * 8 + fr) * KSP + k0];
                bhf[1] = *(const uint32_t*)&Kh[(nt * 8 + fr) * KSP + k0 + 8];
                mma_f16(sacc[nt], qh[ks], bhf);
                mma_f16(sacc[nt], ql[ks], bhf);
            }
            int col = jt * BK + nt * 8 + c2;
            float2 rb0 = *(const float2*)(relp + col);
            float2 rb1 = *(const float2*)(relp + 8 * SEQ + col);
            sacc[nt][0] = __expf(fmaf(sacc[nt][0], 0.125f, rb0.x));
            sacc[nt][1] = __expf(fmaf(sacc[nt][1], 0.125f, rb0.y));
            sacc[nt][2] = __expf(fmaf(sacc[nt][2], 0.125f, rb1.x));
            sacc[nt][3] = __expf(fmaf(sacc[nt][3], 0.125f, rb1.y));
            den0 += sacc[nt][0] + sacc[nt][1];
            den1 += sacc[nt][2] + sacc[nt][3];
        }

        // ---- O += P V (1-term fp16, P rounded) ----
#pragma unroll
        for (int ks2 = 0; ks2 < 8; ks2++) {
            const float* e0 = sacc[2 * ks2];
            const float* e1 = sacc[2 * ks2 + 1];
            uint32_t pa[4];
            pa[0] = pack_one(e0[0], e0[1]);
            pa[1] = pack_one(e0[2], e0[3]);
            pa[2] = pack_one(e1[0], e1[1]);
            pa[3] = pack_one(e1[2], e1[3]);
            const int k0 = ks2 * 16 + c2;
#pragma unroll
            for (int nt2 = 0; nt2 < 8; nt2++) {
                uint32_t vb[2];
                vb[0] = *(const uint32_t*)&Vth[(nt2 * 8 + fr) * VSP + k0];
                vb[1] = *(const uint32_t*)&Vth[(nt2 * 8 + fr) * VSP + k0 + 8];
                mma_f16(oacc[nt2], pa, vb);
            }
        }
    }

    // ---- finalize: scene term, divide, write single fp16 ----
    den0 += __shfl_xor_sync(0xffffffffu, den0, 1);
    den0 += __shfl_xor_sync(0xffffffffu, den0, 2);
    den1 += __shfl_xor_sync(0xffffffffu, den1, 1);
    den1 += __shfl_xor_sync(0xffffffffu, den1, 2);

    const int r0g = q0 + wq + fr;
    const float* w0v = w0g + (b * HEADS + h) * SEQ;
    float wA = w0v[r0g], wB = w0v[r0g + 8];
    float invA = 1.0f / (den0 + wA);
    float invB = 1.0f / (den1 + wB);
    const float* vsc = vs_scene + b * FDIM + h * HD;

#pragma unroll
    for (int nt2 = 0; nt2 < 8; nt2++) {
        int d0 = nt2 * 8 + c2;
        float2 vs2 = *(const float2*)(vsc + d0);
        float ax = (oacc[nt2][0] + wA * vs2.x) * invA;
        float ay = (oacc[nt2][1] + wA * vs2.y) * invA;
        float bx = (oacc[nt2][2] + wB * vs2.x) * invB;
        float by = (oacc[nt2][3] + wB * vs2.y) * invB;
        size_t baseA = (size_t)(b * SEQ + r0g) * FDIM + h * HD + d0;
        size_t baseB = (size_t)(b * SEQ + r0g + 8) * FDIM + h * HD + d0;
        *(uint32_t*)&ahi[baseA] = pack_one(ax, ay);
        *(uint32_t*)&ahi[baseB] = pack_one(bx, by);
    }
}

// ===========================================================================
// Launch
// ===========================================================================
extern "C" void kernel_launch(void* const* d_in, const int* in_sizes, int n_in,
                              void* d_out, int out_size)
{
    (void)in_sizes; (void)n_in; (void)out_size;
    const float* feature = (const float*)d_in[0];
    const float* scene   = (const float*)d_in[1];
    const float* rel     = (const float*)d_in[2];
    const float* Wq = (const float*)d_in[3];  const float* bq = (const float*)d_in[4];
    const float* Wk = (const float*)d_in[5];  const float* bk = (const float*)d_in[6];
    const float* Wv = (const float*)d_in[7];  const float* bv = (const float*)d_in[8];
    const float* Wo = (const float*)d_in[9];  const float* bo = (const float*)d_in[10];
    float* out = (float*)d_out;

    float *qf, *qs, *ks, *vs, *R1, *w0;
    cudaGetSymbolAddress((void**)&qf, g_qf);
    cudaGetSymbolAddress((void**)&qs, g_qs);
    cudaGetSymbolAddress((void**)&ks, g_ks);
    cudaGetSymbolAddress((void**)&vs, g_vs);
    cudaGetSymbolAddress((void**)&R1, g_R1);
    cudaGetSymbolAddress((void**)&w0, g_w0);

    __half *fhi, *flo, *wq, *wk, *wv, *wo;
    __half *qhi, *qlo, *kh, *vh, *ahi;
    cudaGetSymbolAddress((void**)&fhi, g_fhi);
    cudaGetSymbolAddress((void**)&flo, g_flo);
    cudaGetSymbolAddress((void**)&wq,  g_wq);
    cudaGetSymbolAddress((void**)&wk,  g_wk);
    cudaGetSymbolAddress((void**)&wv,  g_wv);
    cudaGetSymbolAddress((void**)&wo,  g_wo);
    cudaGetSymbolAddress((void**)&qhi, g_qhi);
    cudaGetSymbolAddress((void**)&qlo, g_qlo);
    cudaGetSymbolAddress((void**)&kh,  g_kh);
    cudaGetSymbolAddress((void**)&vh,  g_vh);
    cudaGetSymbolAddress((void**)&ahi, g_ahi);

    cudaFuncSetAttribute(gemm_mma,
                         cudaFuncAttributeMaxDynamicSharedMemorySize, GSM_TOT);
    cudaFuncSetAttribute(attn_mma,
                         cudaFuncAttributeMaxDynamicSharedMemorySize, ASM_TOT);

    const int NF = BATCH * NTOK * FDIM;
    const int NW = FDIM * FDIM;

    // Splits / rounds
    split_kernel<<<NF / 1024, 256>>>(feature, fhi, flo, NF);
    dim3 gr(NW / 1024, 4);
    round4_kernel<<<gr, 256>>>(Wq, wq, Wk, wk, Wv, wv, Wo, wo, NW);

    // Scene QKV + R1
    scene_qkv_kernel<<<1536, 256>>>(scene, Wq, bq, Wk, bk, Wv, bv, qs, ks, vs);
    r1_kernel<<<256, 256>>>(rel, R1);

    // Feature QKV (2-term): q -> fp32 + fp16 pair; k, v -> single fp16
    dim3 gq(FDIM / 128, (BATCH * NTOK) / 128);   // (8, 32)
    gemm_mma<<<gq, 256, GSM_TOT>>>(fhi, flo, wq, bq, qf,   qhi, qlo,  FDIM);
    gemm_mma<<<gq, 256, GSM_TOT>>>(fhi, flo, wk, bk, NULL, kh,  NULL, FDIM);
    gemm_mma<<<gq, 256, GSM_TOT>>>(fhi, flo, wv, bv, NULL, vh,  NULL, FDIM);

    // Scene-key closed form weights
    w0_kernel<<<(BATCH * HEADS * SEQ) / 8, 256>>>(qf, qs, ks, R1, w0);

    // Attention (tensor-core, fp16; P single, output single)
    dim3 ga(SEQ / BQ, HEADS, BATCH);   // (16, 16, 4)
    attn_mma<<<ga, 256, ASM_TOT>>>(qhi, qlo, kh, vh, qs, vs, rel, w0, ahi);

    // Output projection -> d_out (fp32), 1-term
    dim3 go(FDIM / 128, (BATCH * SEQ) / 128);    // (8, 64)
    gemm_mma<<<go, 256, GSM_TOT>>>(ahi, NULL, wo, bo, out, NULL, NULL, FDIM);
}